// round 1
// baseline (speedup 1.0000x reference)
#include <cuda_runtime.h>
#include <math.h>

// Problem constants
#define ALPHA   0.2f
#define NEGINF  (-9.0e15f)
constexpr int B_     = 16;
constexpr int N_     = 1024;
constexpr int NFEAT  = 64;
constexpr int NHID   = 64;
constexpr int NCLASS = 32;
constexpr int NHEADS = 4;
constexpr int NW     = N_ / 32;   // adj bitmask words per row

// ---------------- scratch (single __device__ arena, no allocations) ----------
constexpr size_t O_ADJ  = 0;                                   // 524288 u32
constexpr size_t O_WH1  = O_ADJ  + (size_t)B_ * N_ * NW;       // 4,194,304 f32
constexpr size_t O_F1   = O_WH1  + (size_t)NHEADS * B_ * N_ * NHID;
constexpr size_t O_G1   = O_F1   + (size_t)NHEADS * B_ * N_;
constexpr size_t O_M1   = O_G1   + (size_t)NHEADS * B_ * N_;
constexpr size_t O_S1   = O_M1   + (size_t)NHEADS * B_ * N_;
constexpr size_t O_HCAT = O_S1   + (size_t)NHEADS * B_ * N_;   // 4,194,304 f32
constexpr size_t O_WH2  = O_HCAT + (size_t)B_ * N_ * NHEADS * NHID;
constexpr size_t O_F2   = O_WH2  + (size_t)B_ * N_ * NCLASS;
constexpr size_t O_G2   = O_F2   + (size_t)B_ * N_;
constexpr size_t O_M2   = O_G2   + (size_t)B_ * N_;
constexpr size_t O_S2   = O_M2   + (size_t)B_ * N_;
constexpr size_t SCRATCH_TOTAL = O_S2 + (size_t)B_ * N_;

__device__ float g_scratch[SCRATCH_TOTAL];

// ---------------- 1. pack adjacency (int32 0/1 -> bitmask) -------------------
__global__ __launch_bounds__(256)
void pack_adj_kernel(const int* __restrict__ adj) {
    unsigned* bits = reinterpret_cast<unsigned*>(g_scratch) + O_ADJ;
    size_t tid  = (size_t)blockIdx.x * blockDim.x + threadIdx.x;
    size_t w    = tid >> 5;
    int    lane = threadIdx.x & 31;
    int v = adj[w * 32 + lane];
    unsigned word = __ballot_sync(0xffffffffu, v > 0);
    if (lane == 0) bits[w] = word;
}

// ---------------- 2. Wh1 = x @ W_heads[h]  (64x64 tiles, 4x4 microtile) ------
__global__ __launch_bounds__(256)
void gemm_wh1_kernel(const float* __restrict__ x, const float* __restrict__ W) {
    __shared__ float xs[NFEAT][68];   // [k][i] transposed
    __shared__ float Ws[NFEAT][68];   // [k][o]
    int t = threadIdx.x;
    int head = blockIdx.z, b = blockIdx.y, i0 = blockIdx.x * 64;

    const float* Wh_ = W + (size_t)head * NFEAT * NHID;
    for (int idx = t; idx < NFEAT * NHID; idx += 256)
        Ws[idx / NHID][idx % NHID] = Wh_[idx];

    const float* xb = x + ((size_t)b * N_ + i0) * NFEAT;
    for (int idx = t; idx < 64 * NFEAT; idx += 256) {
        int i = idx / NFEAT, k = idx % NFEAT;
        xs[k][i] = xb[idx];
    }
    __syncthreads();

    int tx = t & 15, ty = t >> 4;
    int oo = tx * 4, ii = ty * 4;
    float acc[4][4] = {};
#pragma unroll 16
    for (int k = 0; k < NFEAT; k++) {
        float4 xv = *(const float4*)&xs[k][ii];
        float4 wv = *(const float4*)&Ws[k][oo];
        float xr[4] = {xv.x, xv.y, xv.z, xv.w};
        float wr[4] = {wv.x, wv.y, wv.z, wv.w};
#pragma unroll
        for (int r = 0; r < 4; r++)
#pragma unroll
            for (int c = 0; c < 4; c++)
                acc[r][c] += xr[r] * wr[c];
    }
    float* outb = g_scratch + O_WH1 +
                  (((size_t)head * B_ + b) * N_ + i0) * NHID;
#pragma unroll
    for (int r = 0; r < 4; r++) {
        float4 v = make_float4(acc[r][0], acc[r][1], acc[r][2], acc[r][3]);
        *(float4*)&outb[(size_t)(ii + r) * NHID + oo] = v;
    }
}

// ---------------- 3. f = Wh @ a_src, g = Wh @ a_dst (warp per row) -----------
__global__ __launch_bounds__(256)
void fg_kernel(size_t owh, const float* __restrict__ a, size_t of, size_t og,
               int nout, int rows_per_head) {
    size_t warp = ((size_t)blockIdx.x * blockDim.x + threadIdx.x) >> 5;
    int lane = threadIdx.x & 31;
    const float* ah  = a + (warp / rows_per_head) * 2 * nout;
    const float* row = g_scratch + owh + warp * nout;
    float fv = 0.f, gv = 0.f;
    for (int o = lane; o < nout; o += 32) {
        float v = row[o];
        fv += v * ah[o];
        gv += v * ah[nout + o];
    }
#pragma unroll
    for (int off = 16; off; off >>= 1) {
        fv += __shfl_xor_sync(0xffffffffu, fv, off);
        gv += __shfl_xor_sync(0xffffffffu, gv, off);
    }
    if (lane == 0) {
        g_scratch[of + warp] = fv;
        g_scratch[og + warp] = gv;
    }
}

// ---------------- 4. softmax stats (row max m, row sum s) --------------------
// grid: (N/8, B, Z). warp per row i. Two passes over j using cached g row.
__global__ __launch_bounds__(256)
void stats_kernel(size_t of, size_t og, size_t om, size_t os) {
    __shared__ float gs[N_];
    const unsigned* bits = reinterpret_cast<const unsigned*>(g_scratch) + O_ADJ;
    int t = threadIdx.x, lane = t & 31, wid = t >> 5;
    int b = blockIdx.y, z = blockIdx.z;
    size_t base = ((size_t)z * B_ + b) * N_;
    for (int j = t; j < N_; j += 256) gs[j] = g_scratch[og + base + j];
    __syncthreads();

    int i = blockIdx.x * 8 + wid;
    float fi = g_scratch[of + base + i];
    unsigned w = bits[((size_t)b * N_ + i) * NW + lane];

    float mx = -INFINITY;
#pragma unroll
    for (int jj = 0; jj < 32; jj++) {
        unsigned word = __shfl_sync(0xffffffffu, w, jj);
        float v = fi + gs[jj * 32 + lane];
        v = v > 0.f ? v : ALPHA * v;
        float e = ((word >> lane) & 1u) ? v : NEGINF;
        mx = fmaxf(mx, e);
    }
#pragma unroll
    for (int off = 16; off; off >>= 1)
        mx = fmaxf(mx, __shfl_xor_sync(0xffffffffu, mx, off));

    float sum = 0.f;
#pragma unroll
    for (int jj = 0; jj < 32; jj++) {
        unsigned word = __shfl_sync(0xffffffffu, w, jj);
        float v = fi + gs[jj * 32 + lane];
        v = v > 0.f ? v : ALPHA * v;
        float e = ((word >> lane) & 1u) ? v : NEGINF;
        sum += __expf(e - mx);
    }
#pragma unroll
    for (int off = 16; off; off >>= 1)
        sum += __shfl_xor_sync(0xffffffffu, sum, off);

    if (lane == 0) {
        g_scratch[om + base + i] = mx;
        g_scratch[os + base + i] = sum;
    }
}

// ---------------- 5. attention AV: out_i = (1/s_i) sum_j exp(e_ij-m_i) Wh_j --
// grid (N/64, B, Z). 256 threads, 64(i) x NOUT(o) tile, j tiles of 64.
template <int NOUT, bool ELU>
__global__ __launch_bounds__(256)
void attn_kernel(float* __restrict__ ext_out, int ostride, int headcol,
                 size_t owh, size_t of, size_t og, size_t om, size_t os,
                 size_t oout) {
    constexpr int MO = NOUT / 16;              // 4 or 2 outs per thread
    __shared__ float whs[64][NOUT + 4];        // [j][o]
    __shared__ float ps [64][68];              // [j][i]
    __shared__ float fi[64], mi[64], si[64];

    const unsigned* bits = reinterpret_cast<const unsigned*>(g_scratch) + O_ADJ;
    int t = threadIdx.x;
    int b = blockIdx.y, z = blockIdx.z;
    int i0 = blockIdx.x * 64;
    size_t rbase = ((size_t)z * B_ + b) * N_;
    const float* Whb = g_scratch + owh + rbase * NOUT;
    const float* gv  = g_scratch + og + rbase;
    const unsigned* brow = bits + ((size_t)b * N_ + i0) * NW;

    if (t < 64) {
        fi[t] = g_scratch[of + rbase + i0 + t];
        mi[t] = g_scratch[om + rbase + i0 + t];
        si[t] = g_scratch[os + rbase + i0 + t];
    }

    int tx = t & 15, ty = t >> 4;
    int oo = tx * MO, ii = ty * 4;
    float acc[4][MO] = {};

    for (int j0 = 0; j0 < N_; j0 += 64) {
        __syncthreads();   // protect whs/ps (and first-iter fi/mi/si)
        for (int idx = t; idx < 64 * NOUT; idx += 256)
            whs[idx / NOUT][idx % NOUT] = Whb[(size_t)j0 * NOUT + idx];
#pragma unroll
        for (int kk = 0; kk < 16; kk++) {
            int idx = t + kk * 256;
            int i = idx >> 6, j = idx & 63;
            unsigned word = brow[(size_t)i * NW + ((j0 + j) >> 5)];
            float v = fi[i] + gv[j0 + j];       // g broadcast via L1
            v = v > 0.f ? v : ALPHA * v;
            float e = ((word >> ((j0 + j) & 31)) & 1u) ? v : NEGINF;
            ps[j][i] = __expf(e - mi[i]);
        }
        __syncthreads();
#pragma unroll 8
        for (int k = 0; k < 64; k++) {
            float4 pv = *(const float4*)&ps[k][ii];
            float pr[4] = {pv.x, pv.y, pv.z, pv.w};
            float wr[MO];
            if constexpr (MO == 4) {
                float4 wv = *(const float4*)&whs[k][oo];
                wr[0] = wv.x; wr[1] = wv.y; wr[2] = wv.z; wr[3] = wv.w;
            } else {
                float2 wv = *(const float2*)&whs[k][oo];
                wr[0] = wv.x; wr[1] = wv.y;
            }
#pragma unroll
            for (int r = 0; r < 4; r++)
#pragma unroll
                for (int c = 0; c < MO; c++)
                    acc[r][c] += pr[r] * wr[c];
        }
    }

    float* out = ext_out ? ext_out : (g_scratch + oout);
#pragma unroll
    for (int r = 0; r < 4; r++) {
        int i = ii + r;
        float inv = 1.0f / si[i];
        float* orow = out + ((size_t)b * N_ + i0 + i) * ostride
                          + (size_t)z * headcol + oo;
#pragma unroll
        for (int c = 0; c < MO; c++) {
            float v = acc[r][c] * inv;
            if (ELU) v = v > 0.f ? v : expm1f(v);
            orow[c] = v;
        }
    }
}

// ---------------- 6. Wh2 = h_cat @ W_out  (K=256 in 4 tiles) -----------------
__global__ __launch_bounds__(256)
void gemm_wh2_kernel(const float* __restrict__ Wout) {
    __shared__ float hs[64][68];   // [k][i] transposed
    __shared__ float Ws[64][36];   // [k][o] per k-tile
    int t = threadIdx.x;
    int b = blockIdx.y, i0 = blockIdx.x * 64;
    const float* hb = g_scratch + O_HCAT + ((size_t)b * N_ + i0) * 256;

    int tx = t & 15, ty = t >> 4;
    int oo = tx * 2, ii = ty * 4;
    float acc[4][2] = {};

    for (int kt = 0; kt < 4; kt++) {
        __syncthreads();
        for (int idx = t; idx < 64 * 32; idx += 256) {
            int k = idx / 32, o = idx % 32;
            Ws[k][o] = Wout[((size_t)kt * 64 + k) * 32 + o];
        }
        for (int idx = t; idx < 64 * 64; idx += 256) {
            int i = idx / 64, k = idx % 64;
            hs[k][i] = hb[(size_t)i * 256 + kt * 64 + k];
        }
        __syncthreads();
#pragma unroll 8
        for (int k = 0; k < 64; k++) {
            float4 hv = *(const float4*)&hs[k][ii];
            float2 wv = *(const float2*)&Ws[k][oo];
            float hr[4] = {hv.x, hv.y, hv.z, hv.w};
#pragma unroll
            for (int r = 0; r < 4; r++) {
                acc[r][0] += hr[r] * wv.x;
                acc[r][1] += hr[r] * wv.y;
            }
        }
    }
    float* outb = g_scratch + O_WH2 + ((size_t)b * N_ + i0) * NCLASS;
#pragma unroll
    for (int r = 0; r < 4; r++) {
        float2 v = make_float2(acc[r][0], acc[r][1]);
        *(float2*)&outb[(size_t)(ii + r) * NCLASS + oo] = v;
    }
}

// ---------------- launch -----------------------------------------------------
extern "C" void kernel_launch(void* const* d_in, const int* in_sizes, int n_in,
                              void* d_out, int out_size) {
    const float* x       = (const float*)d_in[0];
    const int*   adj     = (const int*)  d_in[1];
    const float* W_heads = (const float*)d_in[2];
    const float* a_heads = (const float*)d_in[3];
    const float* W_out   = (const float*)d_in[4];
    const float* a_out   = (const float*)d_in[5];
    float* out = (float*)d_out;

    // adj -> bitmask (524288 words, 1 warp per word)
    pack_adj_kernel<<<65536, 256>>>(adj);

    // layer 1
    gemm_wh1_kernel<<<dim3(16, B_, NHEADS), 256>>>(x, W_heads);
    fg_kernel<<<8192, 256>>>(O_WH1, a_heads, O_F1, O_G1, NHID, B_ * N_);
    stats_kernel<<<dim3(N_ / 8, B_, NHEADS), 256>>>(O_F1, O_G1, O_M1, O_S1);
    attn_kernel<NHID, true><<<dim3(N_ / 64, B_, NHEADS), 256>>>(
        nullptr, NHEADS * NHID, NHID, O_WH1, O_F1, O_G1, O_M1, O_S1, O_HCAT);

    // layer 2
    gemm_wh2_kernel<<<dim3(16, B_), 256>>>(W_out);
    fg_kernel<<<2048, 256>>>(O_WH2, a_out, O_F2, O_G2, NCLASS, B_ * N_);
    stats_kernel<<<dim3(N_ / 8, B_, 1), 256>>>(O_F2, O_G2, O_M2, O_S2);
    attn_kernel<NCLASS, false><<<dim3(N_ / 64, B_, 1), 256>>>(
        out, NCLASS, 0, O_WH2, O_F2, O_G2, O_M2, O_S2, 0);
}

// round 2
// speedup vs baseline: 1.9863x; 1.9863x over previous
#include <cuda_runtime.h>
#include <math.h>
#include <stdint.h>

// Problem constants
#define ALPHA   0.2f
constexpr int B_     = 16;
constexpr int N_     = 1024;
constexpr int NFEAT  = 64;
constexpr int NHID   = 64;
constexpr int NCLASS = 32;
constexpr int NHEADS = 4;
constexpr int NW     = N_ / 32;   // adj bitmask words per row

// ---------------- scratch (single __device__ arena, no allocations) ----------
constexpr size_t O_ADJ  = 0;                                   // 524288 u32
constexpr size_t O_WH1  = O_ADJ  + (size_t)B_ * N_ * NW;
constexpr size_t O_F1   = O_WH1  + (size_t)NHEADS * B_ * N_ * NHID;
constexpr size_t O_G1   = O_F1   + (size_t)NHEADS * B_ * N_;
constexpr size_t O_HCAT = O_G1   + (size_t)NHEADS * B_ * N_;
constexpr size_t O_WH2  = O_HCAT + (size_t)B_ * N_ * NHEADS * NHID;
constexpr size_t O_F2   = O_WH2  + (size_t)B_ * N_ * NCLASS;
constexpr size_t O_G2   = O_F2   + (size_t)B_ * N_;
constexpr size_t SCRATCH_TOTAL = O_G2 + (size_t)B_ * N_;

__device__ float g_scratch[SCRATCH_TOTAL];

// ---------------- helpers ----------------------------------------------------
__device__ __forceinline__ uint32_t f2tf32(float v) {
    uint32_t u;
    asm("cvt.rna.tf32.f32 %0, %1;" : "=r"(u) : "f"(v));
    return u;
}

__device__ __forceinline__ void mma_tf32(float* c, const uint32_t* a,
                                         uint32_t b0, uint32_t b1) {
    asm volatile(
        "mma.sync.aligned.m16n8k8.row.col.f32.tf32.tf32.f32 "
        "{%0,%1,%2,%3}, {%4,%5,%6,%7}, {%8,%9}, {%0,%1,%2,%3};"
        : "+f"(c[0]), "+f"(c[1]), "+f"(c[2]), "+f"(c[3])
        : "r"(a[0]), "r"(a[1]), "r"(a[2]), "r"(a[3]), "r"(b0), "r"(b1));
}

// ---------------- 1. pack adjacency (int32 0/1 -> bitmask) -------------------
__global__ __launch_bounds__(256)
void pack_adj_kernel(const int* __restrict__ adj) {
    unsigned* bits = reinterpret_cast<unsigned*>(g_scratch) + O_ADJ;
    size_t tid  = (size_t)blockIdx.x * blockDim.x + threadIdx.x;
    size_t w    = tid >> 5;
    int    lane = threadIdx.x & 31;
    int v = adj[w * 32 + lane];
    unsigned word = __ballot_sync(0xffffffffu, v > 0);
    if (lane == 0) bits[w] = word;
}

// ---------------- 2. Wh1 = x @ W_heads[h]  (64x64 tiles, 4x4 microtile) ------
__global__ __launch_bounds__(256)
void gemm_wh1_kernel(const float* __restrict__ x, const float* __restrict__ W) {
    __shared__ float xs[NFEAT][68];   // [k][i] transposed
    __shared__ float Ws[NFEAT][68];   // [k][o]
    int t = threadIdx.x;
    int head = blockIdx.z, b = blockIdx.y, i0 = blockIdx.x * 64;

    const float* Wh_ = W + (size_t)head * NFEAT * NHID;
    for (int idx = t; idx < NFEAT * NHID; idx += 256)
        Ws[idx / NHID][idx % NHID] = Wh_[idx];

    const float* xb = x + ((size_t)b * N_ + i0) * NFEAT;
    for (int idx = t; idx < 64 * NFEAT; idx += 256) {
        int i = idx / NFEAT, k = idx % NFEAT;
        xs[k][i] = xb[idx];
    }
    __syncthreads();

    int tx = t & 15, ty = t >> 4;
    int oo = tx * 4, ii = ty * 4;
    float acc[4][4] = {};
#pragma unroll 16
    for (int k = 0; k < NFEAT; k++) {
        float4 xv = *(const float4*)&xs[k][ii];
        float4 wv = *(const float4*)&Ws[k][oo];
        float xr[4] = {xv.x, xv.y, xv.z, xv.w};
        float wr[4] = {wv.x, wv.y, wv.z, wv.w};
#pragma unroll
        for (int r = 0; r < 4; r++)
#pragma unroll
            for (int c = 0; c < 4; c++)
                acc[r][c] += xr[r] * wr[c];
    }
    float* outb = g_scratch + O_WH1 +
                  (((size_t)head * B_ + b) * N_ + i0) * NHID;
#pragma unroll
    for (int r = 0; r < 4; r++) {
        float4 v = make_float4(acc[r][0], acc[r][1], acc[r][2], acc[r][3]);
        *(float4*)&outb[(size_t)(ii + r) * NHID + oo] = v;
    }
}

// ---------------- 3. f = Wh @ a_src, g = Wh @ a_dst (warp per row) -----------
__global__ __launch_bounds__(256)
void fg_kernel(size_t owh, const float* __restrict__ a, size_t of, size_t og,
               int nout, int rows_per_head) {
    size_t warp = ((size_t)blockIdx.x * blockDim.x + threadIdx.x) >> 5;
    int lane = threadIdx.x & 31;
    const float* ah  = a + (warp / rows_per_head) * 2 * nout;
    const float* row = g_scratch + owh + warp * nout;
    float fv = 0.f, gv = 0.f;
    for (int o = lane; o < nout; o += 32) {
        float v = row[o];
        fv += v * ah[o];
        gv += v * ah[nout + o];
    }
#pragma unroll
    for (int off = 16; off; off >>= 1) {
        fv += __shfl_xor_sync(0xffffffffu, fv, off);
        gv += __shfl_xor_sync(0xffffffffu, gv, off);
    }
    if (lane == 0) {
        g_scratch[of + warp] = fv;
        g_scratch[og + warp] = gv;
    }
}

// ---------------- 4. fused attention: tf32 MMA + inline softmax --------------
// out_i[o] = sum_j p_ij Wh_j[o] / sum_j p_ij,  p_ij = adj ? exp(leaky(f_i+g_j)) : 0
// No max-subtraction: logits are bounded (|e| < ~30), exp is fp32-safe.
// grid (N/128, B, Z). 256 threads = 8 warps; warp w owns rows [i0+16w, i0+16w+16),
// all NOUT cols. K-loop over j in chunks of 32 (4 mma k-steps of 8).
template <int NOUT, bool ELU>
__global__ __launch_bounds__(256)
void attn_mma_kernel(float* __restrict__ ext_out, int ostride, int headcol,
                     size_t owh, size_t of, size_t og, size_t oout) {
    constexpr int NT  = NOUT / 8;       // n-tiles per warp
    constexpr int WST = NOUT + 8;       // whs row stride (mod 32 == 8 -> no conflicts)
    __shared__ float gs[N_];
    __shared__ float whs[32][WST];      // tf32-rounded Wh chunk [j][o]

    const unsigned* bits = reinterpret_cast<const unsigned*>(g_scratch) + O_ADJ;
    int t = threadIdx.x, lane = t & 31, w = t >> 5;
    int b = blockIdx.y, z = blockIdx.z;
    int i0 = blockIdx.x * 128;
    size_t rbase = ((size_t)z * B_ + b) * N_;
    const float* Whb = g_scratch + owh + rbase * NOUT;

    for (int j = t; j < N_; j += 256) gs[j] = g_scratch[og + rbase + j];

    int r0 = i0 + w * 16 + (lane >> 2);
    int r1 = r0 + 8;
    float f0 = g_scratch[of + rbase + r0];
    float f1 = g_scratch[of + rbase + r1];
    const unsigned* br0 = bits + ((size_t)b * N_ + r0) * NW;
    const unsigned* br1 = bits + ((size_t)b * N_ + r1) * NW;

    float c[NT][4];
#pragma unroll
    for (int nt = 0; nt < NT; nt++)
#pragma unroll
        for (int q = 0; q < 4; q++) c[nt][q] = 0.f;
    float sum0 = 0.f, sum1 = 0.f;
    int cbase = lane & 3;

    for (int jc = 0; jc < NW; jc++) {
        int j0 = jc * 32;
        __syncthreads();
        unsigned w0 = br0[jc], w1 = br1[jc];      // issue early, overlap fill
        // stage Wh[j0:j0+32][:] into smem, pre-rounded to tf32
        for (int idx = t; idx < 32 * NOUT / 4; idx += 256) {
            int e  = idx * 4;
            int jj = e / NOUT, o = e % NOUT;
            float4 v = *(const float4*)&Whb[(size_t)j0 * NOUT + e];
            float4 r;
            r.x = __uint_as_float(f2tf32(v.x));
            r.y = __uint_as_float(f2tf32(v.y));
            r.z = __uint_as_float(f2tf32(v.z));
            r.w = __uint_as_float(f2tf32(v.w));
            *(float4*)&whs[jj][o] = r;
        }
        __syncthreads();

#pragma unroll
        for (int ks = 0; ks < 4; ks++) {
            int bA = ks * 8 + cbase;              // bit/col index within chunk
            int bB = bA + 4;
            float gA = gs[j0 + bA];
            float gB = gs[j0 + bB];

            float vA0 = f0 + gA, vA1 = f1 + gA, vB0 = f0 + gB, vB1 = f1 + gB;
            vA0 = vA0 > 0.f ? vA0 : ALPHA * vA0;
            vA1 = vA1 > 0.f ? vA1 : ALPHA * vA1;
            vB0 = vB0 > 0.f ? vB0 : ALPHA * vB0;
            vB1 = vB1 > 0.f ? vB1 : ALPHA * vB1;
            float p0 = ((w0 >> bA) & 1u) ? __expf(vA0) : 0.f;
            float p1 = ((w1 >> bA) & 1u) ? __expf(vA1) : 0.f;
            float p2 = ((w0 >> bB) & 1u) ? __expf(vB0) : 0.f;
            float p3 = ((w1 >> bB) & 1u) ? __expf(vB1) : 0.f;
            sum0 += p0 + p2;
            sum1 += p1 + p3;

            uint32_t a[4] = {f2tf32(p0), f2tf32(p1), f2tf32(p2), f2tf32(p3)};
#pragma unroll
            for (int nt = 0; nt < NT; nt++) {
                int o = nt * 8 + (lane >> 2);
                uint32_t bb0 = __float_as_uint(whs[bA][o]);
                uint32_t bb1 = __float_as_uint(whs[bB][o]);
                mma_tf32(c[nt], a, bb0, bb1);
            }
        }
    }

    // reduce row sums across the 4 lanes sharing each row
    sum0 += __shfl_xor_sync(0xffffffffu, sum0, 1);
    sum0 += __shfl_xor_sync(0xffffffffu, sum0, 2);
    sum1 += __shfl_xor_sync(0xffffffffu, sum1, 1);
    sum1 += __shfl_xor_sync(0xffffffffu, sum1, 2);
    float inv0 = sum0 > 0.f ? 1.0f / sum0 : 0.f;
    float inv1 = sum1 > 0.f ? 1.0f / sum1 : 0.f;

    float* outp = ext_out ? ext_out : (g_scratch + oout);
    size_t ro0 = ((size_t)b * N_ + r0) * ostride + (size_t)z * headcol;
    size_t ro1 = ((size_t)b * N_ + r1) * ostride + (size_t)z * headcol;
#pragma unroll
    for (int nt = 0; nt < NT; nt++) {
        int oc = nt * 8 + cbase * 2;
        float2 v0 = make_float2(c[nt][0] * inv0, c[nt][1] * inv0);
        float2 v1 = make_float2(c[nt][2] * inv1, c[nt][3] * inv1);
        if (ELU) {
            v0.x = v0.x > 0.f ? v0.x : expm1f(v0.x);
            v0.y = v0.y > 0.f ? v0.y : expm1f(v0.y);
            v1.x = v1.x > 0.f ? v1.x : expm1f(v1.x);
            v1.y = v1.y > 0.f ? v1.y : expm1f(v1.y);
        }
        *(float2*)&outp[ro0 + oc] = v0;
        *(float2*)&outp[ro1 + oc] = v1;
    }
}

// ---------------- 5. Wh2 = h_cat @ W_out  (K=256 in 4 tiles) -----------------
__global__ __launch_bounds__(256)
void gemm_wh2_kernel(const float* __restrict__ Wout) {
    __shared__ float hs[64][68];   // [k][i] transposed
    __shared__ float Ws[64][36];   // [k][o] per k-tile
    int t = threadIdx.x;
    int b = blockIdx.y, i0 = blockIdx.x * 64;
    const float* hb = g_scratch + O_HCAT + ((size_t)b * N_ + i0) * 256;

    int tx = t & 15, ty = t >> 4;
    int oo = tx * 2, ii = ty * 4;
    float acc[4][2] = {};

    for (int kt = 0; kt < 4; kt++) {
        __syncthreads();
        for (int idx = t; idx < 64 * 32; idx += 256) {
            int k = idx / 32, o = idx % 32;
            Ws[k][o] = Wout[((size_t)kt * 64 + k) * 32 + o];
        }
        for (int idx = t; idx < 64 * 64; idx += 256) {
            int i = idx / 64, k = idx % 64;
            hs[k][i] = hb[(size_t)i * 256 + kt * 64 + k];
        }
        __syncthreads();
#pragma unroll 8
        for (int k = 0; k < 64; k++) {
            float4 hv = *(const float4*)&hs[k][ii];
            float2 wv = *(const float2*)&Ws[k][oo];
            float hr[4] = {hv.x, hv.y, hv.z, hv.w};
#pragma unroll
            for (int r = 0; r < 4; r++) {
                acc[r][0] += hr[r] * wv.x;
                acc[r][1] += hr[r] * wv.y;
            }
        }
    }
    float* outb = g_scratch + O_WH2 + ((size_t)b * N_ + i0) * NCLASS;
#pragma unroll
    for (int r = 0; r < 4; r++) {
        float2 v = make_float2(acc[r][0], acc[r][1]);
        *(float2*)&outb[(size_t)(ii + r) * NCLASS + oo] = v;
    }
}

// ---------------- launch -----------------------------------------------------
extern "C" void kernel_launch(void* const* d_in, const int* in_sizes, int n_in,
                              void* d_out, int out_size) {
    const float* x       = (const float*)d_in[0];
    const int*   adj     = (const int*)  d_in[1];
    const float* W_heads = (const float*)d_in[2];
    const float* a_heads = (const float*)d_in[3];
    const float* W_out   = (const float*)d_in[4];
    const float* a_out   = (const float*)d_in[5];
    float* out = (float*)d_out;

    pack_adj_kernel<<<65536, 256>>>(adj);

    // layer 1
    gemm_wh1_kernel<<<dim3(16, B_, NHEADS), 256>>>(x, W_heads);
    fg_kernel<<<8192, 256>>>(O_WH1, a_heads, O_F1, O_G1, NHID, B_ * N_);
    attn_mma_kernel<NHID, true><<<dim3(N_ / 128, B_, NHEADS), 256>>>(
        nullptr, NHEADS * NHID, NHID, O_WH1, O_F1, O_G1, O_HCAT);

    // layer 2
    gemm_wh2_kernel<<<dim3(16, B_), 256>>>(W_out);
    fg_kernel<<<2048, 256>>>(O_WH2, a_out, O_F2, O_G2, NCLASS, B_ * N_);
    attn_mma_kernel<NCLASS, false><<<dim3(N_ / 128, B_, 1), 256>>>(
        out, NCLASS, 0, O_WH2, O_F2, O_G2, 0);
}

// round 10
// speedup vs baseline: 2.1453x; 1.0800x over previous
#include <cuda_runtime.h>
#include <math.h>
#include <stdint.h>

#define ALPHA  0.2f
#define LOG2E  1.4426950408889634f
constexpr int B_     = 16;
constexpr int N_     = 1024;
constexpr int NFEAT  = 64;
constexpr int NHID   = 64;
constexpr int NCLASS = 32;
constexpr int NHEADS = 4;
constexpr int NW     = N_ / 32;

// ---------------- scratch arena ----------------------------------------------
constexpr size_t O_ADJ  = 0;                                      // bitmask
constexpr size_t O_WH1  = O_ADJ  + (size_t)B_ * N_ * NW;          // fp32 Wh1
constexpr size_t O_WT1  = O_WH1  + (size_t)NHEADS * B_ * N_ * NHID; // tf32 pair-interleaved
constexpr size_t O_F1   = O_WT1  + (size_t)NHEADS * B_ * N_ * NHID;
constexpr size_t O_G1   = O_F1   + (size_t)NHEADS * B_ * N_;
constexpr size_t O_HCAT = O_G1   + (size_t)NHEADS * B_ * N_;
constexpr size_t O_WH2  = O_HCAT + (size_t)B_ * N_ * NHEADS * NHID;
constexpr size_t O_WT2  = O_WH2  + (size_t)B_ * N_ * NCLASS;
constexpr size_t O_F2   = O_WT2  + (size_t)B_ * N_ * NCLASS;
constexpr size_t O_G2   = O_F2   + (size_t)B_ * N_;
constexpr size_t SCRATCH_TOTAL = O_G2 + (size_t)B_ * N_;

__device__ float g_scratch[SCRATCH_TOTAL];

// ---------------- helpers ----------------------------------------------------
__device__ __forceinline__ uint32_t f2tf32(float v) {
    uint32_t u;
    asm("cvt.rna.tf32.f32 %0, %1;" : "=r"(u) : "f"(v));
    return u;
}
__device__ __forceinline__ float ex2f(float x) {
    float r;
    asm("ex2.approx.ftz.f32 %0, %1;" : "=f"(r) : "f"(x));
    return r;
}
__device__ __forceinline__ void mma_tf32(float* c, const uint32_t* a,
                                         uint32_t b0, uint32_t b1) {
    asm volatile(
        "mma.sync.aligned.m16n8k8.row.col.f32.tf32.tf32.f32 "
        "{%0,%1,%2,%3}, {%4,%5,%6,%7}, {%8,%9}, {%0,%1,%2,%3};"
        : "+f"(c[0]), "+f"(c[1]), "+f"(c[2]), "+f"(c[3])
        : "r"(a[0]), "r"(a[1]), "r"(a[2]), "r"(a[3]), "r"(b0), "r"(b1));
}
// pair-interleaved index within a 64-row chunk block:
// jl in [0,64): slot = (jl>>3)*4 + (jl&3) in [0,32), half = (jl>>2)&1
// offset (floats) = slot*(2*NOUT) + o*2 + half
__device__ __forceinline__ int i2_off(int jl, int o, int nout) {
    int slot = ((jl >> 3) << 2) + (jl & 3);
    int half = (jl >> 2) & 1;
    return slot * (nout * 2) + o * 2 + half;
}
// masked logit -> -inf bits when mask==0 (single LOP3 after shifts)
__device__ __forceinline__ float mask_logit(float v, unsigned w, int bit) {
    uint32_t m = (uint32_t)(((int)(w << (31 - bit))) >> 31);
    uint32_t b = (__float_as_uint(v) & m) | (~m & 0xFF800000u);
    return __uint_as_float(b);
}

// ---------------- 1. pack adjacency ------------------------------------------
__global__ __launch_bounds__(256)
void pack_adj_kernel(const int* __restrict__ adj) {
    unsigned* bits = reinterpret_cast<unsigned*>(g_scratch) + O_ADJ;
    size_t tid  = (size_t)blockIdx.x * blockDim.x + threadIdx.x;
    size_t w    = tid >> 5;
    int    lane = threadIdx.x & 31;
    int v = adj[w * 32 + lane];
    unsigned word = __ballot_sync(0xffffffffu, v > 0);
    if (lane == 0) bits[w] = word;
}

// ---------------- 2. Wh1 = x @ W_heads[h] (+ tf32 interleaved copy) ----------
__global__ __launch_bounds__(256)
void gemm_wh1_kernel(const float* __restrict__ x, const float* __restrict__ W) {
    __shared__ float xs[NFEAT][68];
    __shared__ float Ws[NFEAT][68];
    int t = threadIdx.x;
    int head = blockIdx.z, b = blockIdx.y, i0 = blockIdx.x * 64;

    const float* Wh_ = W + (size_t)head * NFEAT * NHID;
    for (int idx = t; idx < NFEAT * NHID; idx += 256)
        Ws[idx / NHID][idx % NHID] = Wh_[idx];

    const float* xb = x + ((size_t)b * N_ + i0) * NFEAT;
    for (int idx = t; idx < 64 * NFEAT; idx += 256) {
        int i = idx / NFEAT, k = idx % NFEAT;
        xs[k][i] = xb[idx];
    }
    __syncthreads();

    int tx = t & 15, ty = t >> 4;
    int oo = tx * 4, ii = ty * 4;
    float acc[4][4] = {};
#pragma unroll 16
    for (int k = 0; k < NFEAT; k++) {
        float4 xv = *(const float4*)&xs[k][ii];
        float4 wv = *(const float4*)&Ws[k][oo];
        float xr[4] = {xv.x, xv.y, xv.z, xv.w};
        float wr[4] = {wv.x, wv.y, wv.z, wv.w};
#pragma unroll
        for (int r = 0; r < 4; r++)
#pragma unroll
            for (int c = 0; c < 4; c++)
                acc[r][c] += xr[r] * wr[c];
    }
    float* outb = g_scratch + O_WH1 + (((size_t)head * B_ + b) * N_ + i0) * NHID;
    float* wtb  = g_scratch + O_WT1 + (((size_t)head * B_ + b) * N_ + i0) * NHID;
#pragma unroll
    for (int r = 0; r < 4; r++) {
        float4 v = make_float4(acc[r][0], acc[r][1], acc[r][2], acc[r][3]);
        *(float4*)&outb[(size_t)(ii + r) * NHID + oo] = v;
        int jl = ii + r;
#pragma unroll
        for (int c = 0; c < 4; c++)
            wtb[i2_off(jl, oo + c, NHID)] = __uint_as_float(f2tf32(acc[r][c]));
    }
}

// ---------------- 3. f,g (scaled by LOG2E) -----------------------------------
__global__ __launch_bounds__(256)
void fg_kernel(size_t owh, const float* __restrict__ a, size_t of, size_t og,
               int nout, int rows_per_head) {
    size_t warp = ((size_t)blockIdx.x * blockDim.x + threadIdx.x) >> 5;
    int lane = threadIdx.x & 31;
    const float* ah  = a + (warp / rows_per_head) * 2 * nout;
    const float* row = g_scratch + owh + warp * nout;
    float fv = 0.f, gv = 0.f;
    for (int o = lane; o < nout; o += 32) {
        float v = row[o];
        fv += v * ah[o];
        gv += v * ah[nout + o];
    }
#pragma unroll
    for (int off = 16; off; off >>= 1) {
        fv += __shfl_xor_sync(0xffffffffu, fv, off);
        gv += __shfl_xor_sync(0xffffffffu, gv, off);
    }
    if (lane == 0) {
        g_scratch[of + warp] = fv * LOG2E;
        g_scratch[og + warp] = gv * LOG2E;
    }
}

// ---------------- 4. fused attention (tf32 MMA, inline softmax) --------------
// grid (N/128, B, Z), 256 thr = 8 warps; warp w: rows [i0+16w, i0+16w+16).
// j-chunks of 64; B operands pair-interleaved tf32 (one LDS.64 per mma).
template <int NOUT, bool ELU>
__global__ __launch_bounds__(256)
void attn_mma_kernel(float* __restrict__ ext_out, int ostride, int headcol,
                     size_t owt, size_t of, size_t og, size_t oout) {
    constexpr int NT = NOUT / 8;
    constexpr int S2 = (NOUT == 64) ? 68 : 36;   // float2 stride, ==4 mod 16
    __shared__ float  gs[N_];
    __shared__ float2 whs2[32][S2];

    const unsigned* bits = reinterpret_cast<const unsigned*>(g_scratch) + O_ADJ;
    int t = threadIdx.x, lane = t & 31, w = t >> 5;
    int b = blockIdx.y, z = blockIdx.z;
    int i0 = blockIdx.x * 128;
    size_t rbase = ((size_t)z * B_ + b) * N_;
    const float* Wtb = g_scratch + owt + rbase * NOUT;

    for (int j = t; j < N_; j += 256) gs[j] = g_scratch[og + rbase + j];

    int r0 = i0 + w * 16 + (lane >> 2);
    int r1 = r0 + 8;
    float f0 = g_scratch[of + rbase + r0];
    float f1 = g_scratch[of + rbase + r1];
    const unsigned* br0 = bits + ((size_t)b * N_ + r0) * NW;
    const unsigned* br1 = bits + ((size_t)b * N_ + r1) * NW;

    float c[NT][4];
#pragma unroll
    for (int nt = 0; nt < NT; nt++)
#pragma unroll
        for (int q = 0; q < 4; q++) c[nt][q] = 0.f;
    float sum0 = 0.f, sum1 = 0.f;
    int cbase = lane & 3, qo = lane >> 2;

    for (int jc = 0; jc < N_ / 64; jc++) {
        int j0 = jc * 64;
        __syncthreads();
        uint2 mw0 = *(const uint2*)(br0 + 2 * jc);
        uint2 mw1 = *(const uint2*)(br1 + 2 * jc);
        // stage pre-tf32 pair-interleaved chunk (contiguous copy)
        const float4* src = (const float4*)(Wtb + (size_t)j0 * NOUT);
#pragma unroll
        for (int u = 0; u < (64 * NOUT / 4) / 256; u++) {
            int idx = t + u * 256;
            int e2 = idx * 2;                  // float2 index in block
            int slot = e2 / NOUT, o2 = e2 & (NOUT - 1);
            *(float4*)((float*)&whs2[slot][0] + o2 * 2) = src[idx];
        }
        __syncthreads();

#pragma unroll
        for (int ks = 0; ks < 8; ks++) {
            unsigned wr0 = (ks < 4) ? mw0.x : mw0.y;
            unsigned wr1 = (ks < 4) ? mw1.x : mw1.y;
            int bA = ((ks & 3) << 3) + cbase, bB = bA + 4;
            float gA = gs[j0 + (ks << 3) + cbase];
            float gB = gs[j0 + (ks << 3) + cbase + 4];

            float vA0 = f0 + gA, vA1 = f1 + gA, vB0 = f0 + gB, vB1 = f1 + gB;
            vA0 = fmaxf(vA0, ALPHA * vA0);     // leaky (slope<1, commutes)
            vA1 = fmaxf(vA1, ALPHA * vA1);
            vB0 = fmaxf(vB0, ALPHA * vB0);
            vB1 = fmaxf(vB1, ALPHA * vB1);
            float p0 = ex2f(mask_logit(vA0, wr0, bA));
            float p1 = ex2f(mask_logit(vA1, wr1, bA));
            float p2 = ex2f(mask_logit(vB0, wr0, bB));
            float p3 = ex2f(mask_logit(vB1, wr1, bB));
            sum0 += p0 + p2;
            sum1 += p1 + p3;

            uint32_t a[4] = {f2tf32(p0), f2tf32(p1), f2tf32(p2), f2tf32(p3)};
            const float2* wrow = &whs2[(ks << 2) + cbase][0];
#pragma unroll
            for (int nt = 0; nt < NT; nt++) {
                float2 bv = wrow[nt * 8 + qo];
                mma_tf32(c[nt], a, __float_as_uint(bv.x), __float_as_uint(bv.y));
            }
        }
    }

    sum0 += __shfl_xor_sync(0xffffffffu, sum0, 1);
    sum0 += __shfl_xor_sync(0xffffffffu, sum0, 2);
    sum1 += __shfl_xor_sync(0xffffffffu, sum1, 1);
    sum1 += __shfl_xor_sync(0xffffffffu, sum1, 2);
    float inv0 = sum0 > 0.f ? 1.0f / sum0 : 0.f;
    float inv1 = sum1 > 0.f ? 1.0f / sum1 : 0.f;

    float* outp = ext_out ? ext_out : (g_scratch + oout);
    size_t ro0 = ((size_t)b * N_ + r0) * ostride + (size_t)z * headcol;
    size_t ro1 = ((size_t)b * N_ + r1) * ostride + (size_t)z * headcol;
#pragma unroll
    for (int nt = 0; nt < NT; nt++) {
        int oc = nt * 8 + cbase * 2;
        float2 v0 = make_float2(c[nt][0] * inv0, c[nt][1] * inv0);
        float2 v1 = make_float2(c[nt][2] * inv1, c[nt][3] * inv1);
        if (ELU) {
            v0.x = v0.x > 0.f ? v0.x : expm1f(v0.x);
            v0.y = v0.y > 0.f ? v0.y : expm1f(v0.y);
            v1.x = v1.x > 0.f ? v1.x : expm1f(v1.x);
            v1.y = v1.y > 0.f ? v1.y : expm1f(v1.y);
        }
        *(float2*)&outp[ro0 + oc] = v0;
        *(float2*)&outp[ro1 + oc] = v1;
    }
}

// ---------------- 5. Wh2 = h_cat @ W_out (+ tf32 interleaved copy) -----------
__global__ __launch_bounds__(256)
void gemm_wh2_kernel(const float* __restrict__ Wout) {
    __shared__ float hs[64][68];
    __shared__ float Ws[64][36];
    int t = threadIdx.x;
    int b = blockIdx.y, i0 = blockIdx.x * 64;
    const float* hb = g_scratch + O_HCAT + ((size_t)b * N_ + i0) * 256;

    int tx = t & 15, ty = t >> 4;
    int oo = tx * 2, ii = ty * 4;
    float acc[4][2] = {};

    for (int kt = 0; kt < 4; kt++) {
        __syncthreads();
        for (int idx = t; idx < 64 * 32; idx += 256) {
            int k = idx / 32, o = idx % 32;
            Ws[k][o] = Wout[((size_t)kt * 64 + k) * 32 + o];
        }
        for (int idx = t; idx < 64 * 64; idx += 256) {
            int i = idx / 64, k = idx % 64;
            hs[k][i] = hb[(size_t)i * 256 + kt * 64 + k];
        }
        __syncthreads();
#pragma unroll 8
        for (int k = 0; k < 64; k++) {
            float4 hv = *(const float4*)&hs[k][ii];
            float2 wv = *(const float2*)&Ws[k][oo];
            float hr[4] = {hv.x, hv.y, hv.z, hv.w};
#pragma unroll
            for (int r = 0; r < 4; r++) {
                acc[r][0] += hr[r] * wv.x;
                acc[r][1] += hr[r] * wv.y;
            }
        }
    }
    float* outb = g_scratch + O_WH2 + ((size_t)b * N_ + i0) * NCLASS;
    float* wtb  = g_scratch + O_WT2 + ((size_t)b * N_ + i0) * NCLASS;
#pragma unroll
    for (int r = 0; r < 4; r++) {
        float2 v = make_float2(acc[r][0], acc[r][1]);
        *(float2*)&outb[(size_t)(ii + r) * NCLASS + oo] = v;
        int jl = ii + r;
#pragma unroll
        for (int c2 = 0; c2 < 2; c2++)
            wtb[i2_off(jl, oo + c2, NCLASS)] = __uint_as_float(f2tf32(acc[r][c2]));
    }
}

// ---------------- launch -----------------------------------------------------
extern "C" void kernel_launch(void* const* d_in, const int* in_sizes, int n_in,
                              void* d_out, int out_size) {
    const float* x       = (const float*)d_in[0];
    const int*   adj     = (const int*)  d_in[1];
    const float* W_heads = (const float*)d_in[2];
    const float* a_heads = (const float*)d_in[3];
    const float* W_out   = (const float*)d_in[4];
    const float* a_out   = (const float*)d_in[5];
    float* out = (float*)d_out;

    pack_adj_kernel<<<65536, 256>>>(adj);

    // layer 1
    gemm_wh1_kernel<<<dim3(16, B_, NHEADS), 256>>>(x, W_heads);
    fg_kernel<<<8192, 256>>>(O_WH1, a_heads, O_F1, O_G1, NHID, B_ * N_);
    attn_mma_kernel<NHID, true><<<dim3(N_ / 128, B_, NHEADS), 256>>>(
        nullptr, NHEADS * NHID, NHID, O_WT1, O_F1, O_G1, O_HCAT);

    // layer 2
    gemm_wh2_kernel<<<dim3(16, B_), 256>>>(W_out);
    fg_kernel<<<2048, 256>>>(O_WH2, a_out, O_F2, O_G2, NCLASS, B_ * N_);
    attn_mma_kernel<NCLASS, false><<<dim3(N_ / 128, B_, 1), 256>>>(
        out, NCLASS, 0, O_WT2, O_F2, O_G2, 0);
}